// round 1
// baseline (speedup 1.0000x reference)
#include <cuda_runtime.h>

#define SS 30
#define SP 900          // 30*30
#define S4 810000       // 30^4
#define NB 2

// Scratch activations: [b][ch(20)][h1][w1][h2*30+w2]
__device__ float g_t1[NB * 20 * S4];
__device__ float g_t2[NB * 20 * S4];
// Packed weights: branch 0 = original, branch 1 = kernel dims (h1w1)<->(h2w2) swapped
__device__ float g_W1[9 * 9 * 20];          // [to][ti][co20]
__device__ float g_W2[2 * 9 * 10 * 9 * 10]; // [br][to][ci][ti][co10]
__device__ float g_W3[2 * 9 * 10 * 9];      // [br][to][ci][ti]

// ---------------------------------------------------------------------------
// Weight prep: build fused / permuted weight tensors.
// w'(a,b,c,d) = w(c,d,a,b)  (swap outer/inner kernel dim pairs)
// ---------------------------------------------------------------------------
__global__ void prep_kernel(const float* __restrict__ w1,
                            const float* __restrict__ w2,
                            const float* __restrict__ w3) {
    int tid = blockIdx.x * blockDim.x + threadIdx.x;
    int stride = gridDim.x * blockDim.x;
    // W1: [to][ti][co20], co<10 -> w1, co>=10 -> permuted w1
    for (int i = tid; i < 9 * 9 * 20; i += stride) {
        int co = i % 20;
        int ti = (i / 20) % 9;
        int to = i / 180;
        g_W1[i] = (co < 10) ? w1[co * 81 + to * 9 + ti]
                            : w1[(co - 10) * 81 + ti * 9 + to];
    }
    // W2: [br][to][ci][ti][co10]
    for (int i = tid; i < 16200; i += stride) {
        int co = i % 10;
        int ti = (i / 10) % 9;
        int ci = (i / 90) % 10;
        int to = (i / 900) % 9;
        int br = i / 8100;
        g_W2[i] = (br == 0) ? w2[(co * 10 + ci) * 81 + to * 9 + ti]
                            : w2[(co * 10 + ci) * 81 + ti * 9 + to];
    }
    // W3: [br][to][ci][ti]
    for (int i = tid; i < 1620; i += stride) {
        int ti = i % 9;
        int ci = (i / 9) % 10;
        int to = (i / 90) % 9;
        int br = i / 810;
        g_W3[i] = (br == 0) ? w3[ci * 81 + to * 9 + ti]
                            : w3[ci * 81 + ti * 9 + to];
    }
}

// ---------------------------------------------------------------------------
// conv1: x (1 ch) -> t1 (20 ch), relu.  One CTA per (b,h1,w1).
// 600 threads: cb=tid/150 -> co block of 5 (4 blocks = 20 co);
// rem=tid%150: h2=rem/5, w2 group of 6 (5 groups = 30).
// ---------------------------------------------------------------------------
__global__ __launch_bounds__(600)
void conv1_kernel(const float* __restrict__ x, const float* __restrict__ b1) {
    __shared__ float sIn[32 * 33];  // padded (h2,w2) plane, stride 33 vs bank conflicts
    __shared__ float sW[9 * 9 * 20];
    __shared__ float sB[20];
    int bid = blockIdx.x;
    int b = bid / SP;
    int rem = bid % SP;
    int h1 = rem / SS, w1 = rem % SS;
    int tid = threadIdx.x;

    for (int i = tid; i < 1620; i += 600) sW[i] = g_W1[i];
    if (tid < 20) sB[tid] = b1[tid % 10];
    for (int i = tid; i < 32 * 33; i += 600) sIn[i] = 0.f;  // borders stay zero

    int cb = tid / 150;
    int r2 = tid % 150;
    int h2 = r2 / 5;
    int w2_0 = (r2 % 5) * 6;
    int co0 = cb * 5;

    float acc[5][6];
#pragma unroll
    for (int c = 0; c < 5; c++)
#pragma unroll
        for (int p = 0; p < 6; p++) acc[c][p] = 0.f;

    const float* xb = x + (size_t)b * S4;

#pragma unroll 1
    for (int to = 0; to < 9; to++) {
        int H = h1 + to / 3 - 1, W = w1 + to % 3 - 1;
        bool ok = ((unsigned)H < SS) && ((unsigned)W < SS);
        const float* plane = xb + (H * SS + W) * SP;
        __syncthreads();
        for (int i = tid; i < SP; i += 600) {
            int r = i / SS, c2 = i % SS;
            sIn[(r + 1) * 33 + c2 + 1] = ok ? plane[i] : 0.f;
        }
        __syncthreads();
#pragma unroll
        for (int dh2 = 0; dh2 < 3; dh2++) {
            const float* row = &sIn[(h2 + dh2) * 33 + w2_0];
            float in[8];
#pragma unroll
            for (int j = 0; j < 8; j++) in[j] = row[j];
#pragma unroll
            for (int dw2 = 0; dw2 < 3; dw2++) {
                const float* wp = &sW[(to * 9 + dh2 * 3 + dw2) * 20 + co0];
#pragma unroll
                for (int c = 0; c < 5; c++) {
                    float w = wp[c];
#pragma unroll
                    for (int p = 0; p < 6; p++)
                        acc[c][p] = fmaf(in[p + dw2], w, acc[c][p]);
                }
            }
        }
    }

#pragma unroll
    for (int c = 0; c < 5; c++) {
        int co = co0 + c;
        float bias = sB[co];
        float* dst = g_t1 + (((size_t)(b * 20 + co) * SP) + h1 * SS + w1) * SP +
                     h2 * SS + w2_0;
#pragma unroll
        for (int p = 0; p < 6; p++) {
            float v = acc[c][p] + bias;
            dst[p] = v > 0.f ? v : 0.f;
        }
    }
}

// ---------------------------------------------------------------------------
// conv2: t1 -> t2, block-diagonal 20->20 (10->10 per branch), relu.
// One CTA per (b, br, h1, w1): 300 threads, thread tile = 6 w2-pos x 5 co.
// Dynamic smem: 10 input planes (10*1056) + branch weights (8100).
// ---------------------------------------------------------------------------
__global__ __launch_bounds__(300)
void conv2_kernel(const float* __restrict__ b2) {
    extern __shared__ float smem[];
    float* sIn = smem;          // 10 * 1056
    float* sW = smem + 10560;   // 8100
    __shared__ float sB[10];

    int bid = blockIdx.x;
    int w1 = bid % SS;
    int t = bid / SS;
    int h1 = t % SS;
    t /= SS;
    int br = t & 1;
    int b = t >> 1;
    int tid = threadIdx.x;

    for (int i = tid; i < 8100; i += 300) sW[i] = g_W2[br * 8100 + i];
    if (tid < 10) sB[tid] = b2[tid];
    for (int i = tid; i < 10560; i += 300) sIn[i] = 0.f;

    int cb = tid / 150;
    int r2 = tid % 150;
    int h2 = r2 / 5;
    int w2_0 = (r2 % 5) * 6;
    int co0 = cb * 5;

    float acc[5][6];
#pragma unroll
    for (int c = 0; c < 5; c++)
#pragma unroll
        for (int p = 0; p < 6; p++) acc[c][p] = 0.f;

    const float* tbase = g_t1 + (size_t)(b * 20 + br * 10) * S4;

#pragma unroll 1
    for (int to = 0; to < 9; to++) {
        int H = h1 + to / 3 - 1, W = w1 + to % 3 - 1;
        bool ok = ((unsigned)H < SS) && ((unsigned)W < SS);
        int poff = (H * SS + W) * SP;
        __syncthreads();
#pragma unroll 1
        for (int ci = 0; ci < 10; ci++) {
            const float* plane = tbase + (size_t)ci * S4 + poff;
            float* s = sIn + ci * 1056;
            for (int i = tid; i < SP; i += 300) {
                int r = i / SS, c2 = i % SS;
                s[(r + 1) * 33 + c2 + 1] = ok ? plane[i] : 0.f;
            }
        }
        __syncthreads();
#pragma unroll 1
        for (int ci = 0; ci < 10; ci++) {
            const float* sc = sIn + ci * 1056;
            const float* wci = sW + (to * 10 + ci) * 90;  // [ti(9)][co10]
#pragma unroll
            for (int dh2 = 0; dh2 < 3; dh2++) {
                const float* row = sc + (h2 + dh2) * 33 + w2_0;
                float in[8];
#pragma unroll
                for (int j = 0; j < 8; j++) in[j] = row[j];
#pragma unroll
                for (int dw2 = 0; dw2 < 3; dw2++) {
                    const float* wp = wci + (dh2 * 3 + dw2) * 10 + co0;
#pragma unroll
                    for (int c = 0; c < 5; c++) {
                        float w = wp[c];
#pragma unroll
                        for (int p = 0; p < 6; p++)
                            acc[c][p] = fmaf(in[p + dw2], w, acc[c][p]);
                    }
                }
            }
        }
    }

#pragma unroll
    for (int c = 0; c < 5; c++) {
        int cog = br * 10 + co0 + c;
        float bias = sB[co0 + c];
        float* dst = g_t2 + ((size_t)(b * 20 + cog) * SP + h1 * SS + w1) * SP +
                     h2 * SS + w2_0;
#pragma unroll
        for (int p = 0; p < 6; p++) {
            float v = acc[c][p] + bias;
            dst[p] = v > 0.f ? v : 0.f;
        }
    }
}

// ---------------------------------------------------------------------------
// conv3 + final sum: t2 (20ch) -> out = relu(convA + b3) + relu(convB + b3).
// One CTA per (b,h1,w1): 300 threads, thread tile = 3 w2-pos x 2 branches.
// Dynamic smem: 20 input planes (20*1056) + weights (1620).
// ---------------------------------------------------------------------------
__global__ __launch_bounds__(300)
void conv3_kernel(const float* __restrict__ b3, float* __restrict__ out) {
    extern __shared__ float smem[];
    float* sIn = smem;          // 20 * 1056
    float* sW = smem + 21120;   // 1620

    int bid = blockIdx.x;
    int b = bid / SP;
    int rem = bid % SP;
    int h1 = rem / SS, w1 = rem % SS;
    int tid = threadIdx.x;

    for (int i = tid; i < 1620; i += 300) sW[i] = g_W3[i];
    for (int i = tid; i < 21120; i += 300) sIn[i] = 0.f;

    int h2 = tid / 10;
    int w2_0 = (tid % 10) * 3;

    float accA[3] = {0.f, 0.f, 0.f};
    float accB[3] = {0.f, 0.f, 0.f};
    const float* tbase = g_t2 + (size_t)b * 20 * S4;

#pragma unroll 1
    for (int to = 0; to < 9; to++) {
        int H = h1 + to / 3 - 1, W = w1 + to % 3 - 1;
        bool ok = ((unsigned)H < SS) && ((unsigned)W < SS);
        int poff = (H * SS + W) * SP;
        __syncthreads();
#pragma unroll 1
        for (int ch = 0; ch < 20; ch++) {
            const float* plane = tbase + (size_t)ch * S4 + poff;
            float* s = sIn + ch * 1056;
            for (int i = tid; i < SP; i += 300) {
                int r = i / SS, c2 = i % SS;
                s[(r + 1) * 33 + c2 + 1] = ok ? plane[i] : 0.f;
            }
        }
        __syncthreads();
#pragma unroll 1
        for (int ci = 0; ci < 10; ci++) {
            const float* sA = sIn + ci * 1056;
            const float* sBp = sIn + (10 + ci) * 1056;
            const float* wA = sW + (to * 10 + ci) * 9;
            const float* wB = sW + 810 + (to * 10 + ci) * 9;
#pragma unroll
            for (int dh2 = 0; dh2 < 3; dh2++) {
                const float* rowA = sA + (h2 + dh2) * 33 + w2_0;
                const float* rowB = sBp + (h2 + dh2) * 33 + w2_0;
                float inA[5], inB[5];
#pragma unroll
                for (int j = 0; j < 5; j++) {
                    inA[j] = rowA[j];
                    inB[j] = rowB[j];
                }
#pragma unroll
                for (int dw2 = 0; dw2 < 3; dw2++) {
                    float wa = wA[dh2 * 3 + dw2];
                    float wb = wB[dh2 * 3 + dw2];
#pragma unroll
                    for (int p = 0; p < 3; p++) {
                        accA[p] = fmaf(inA[p + dw2], wa, accA[p]);
                        accB[p] = fmaf(inB[p + dw2], wb, accB[p]);
                    }
                }
            }
        }
    }

    float bv = b3[0];
    float* dst = out + (size_t)b * S4 + (h1 * SS + w1) * SP + h2 * SS + w2_0;
#pragma unroll
    for (int p = 0; p < 3; p++) {
        float va = accA[p] + bv;
        va = va > 0.f ? va : 0.f;
        float vb = accB[p] + bv;
        vb = vb > 0.f ? vb : 0.f;
        dst[p] = va + vb;
    }
}

// ---------------------------------------------------------------------------
extern "C" void kernel_launch(void* const* d_in, const int* in_sizes, int n_in,
                              void* d_out, int out_size) {
    const float* x = (const float*)d_in[0];
    const float* w1 = (const float*)d_in[1];
    const float* b1 = (const float*)d_in[2];
    const float* w2 = (const float*)d_in[3];
    const float* b2 = (const float*)d_in[4];
    const float* w3 = (const float*)d_in[5];
    const float* b3 = (const float*)d_in[6];
    float* out = (float*)d_out;

    const int smem2 = (10560 + 8100) * 4;   // 74640 B
    const int smem3 = (21120 + 1620) * 4;   // 90960 B
    cudaFuncSetAttribute(conv2_kernel,
                         cudaFuncAttributeMaxDynamicSharedMemorySize, smem2);
    cudaFuncSetAttribute(conv3_kernel,
                         cudaFuncAttributeMaxDynamicSharedMemorySize, smem3);

    prep_kernel<<<32, 256>>>(w1, w2, w3);
    conv1_kernel<<<NB * SP, 600>>>(x, b1);
    conv2_kernel<<<NB * 2 * SP, 300, smem2>>>(b2);
    conv3_kernel<<<NB * SP, 300, smem3>>>(b3, out);
}

// round 2
// speedup vs baseline: 1.2817x; 1.2817x over previous
#include <cuda_runtime.h>

#define SS 30
#define SP 900          // 30*30
#define S4 810000       // 30^4
#define NB 2

typedef unsigned long long ull;

// Scratch activations
__device__ __align__(16) float g_t1[NB * 20 * S4];                // [b][ch20][h1w1][pos]
__device__ __align__(16) float g_t2[NB * 10 * SP * SP * 2];       // [b][co10][h1w1][pos][br2]
// Packed weights
__device__ __align__(16) float g_W1[9 * 9 * 20];                  // [to][ti][co20]
__device__ __align__(16) float g_W2[2 * 9 * 10 * 9 * 10];         // [br][to][ci][ti][co10]
__device__ __align__(16) float g_W3[9 * 10 * 9 * 2];              // [to][ci][ti][br2]

#define PACK2(d, a, b)  asm("mov.b64 %0, {%1, %2};" : "=l"(d) : "f"(a), "f"(b))
#define FMA2(d, a, b)   asm("fma.rn.f32x2 %0, %1, %2, %0;" : "+l"(d) : "l"(a), "l"(b))
#define UNPACK2(lo, hi, d) asm("mov.b64 {%0, %1}, %2;" : "=f"(lo), "=f"(hi) : "l"(d))

// ---------------------------------------------------------------------------
// Weight prep.  Branch 1 = kernel dims (h1w1)<->(h2w2) swapped.
// ---------------------------------------------------------------------------
__global__ void prep_kernel(const float* __restrict__ w1,
                            const float* __restrict__ w2,
                            const float* __restrict__ w3) {
    int tid = blockIdx.x * blockDim.x + threadIdx.x;
    int stride = gridDim.x * blockDim.x;
    for (int i = tid; i < 9 * 9 * 20; i += stride) {
        int co = i % 20;
        int ti = (i / 20) % 9;
        int to = i / 180;
        g_W1[i] = (co < 10) ? w1[co * 81 + to * 9 + ti]
                            : w1[(co - 10) * 81 + ti * 9 + to];
    }
    for (int i = tid; i < 16200; i += stride) {
        int co = i % 10;
        int ti = (i / 10) % 9;
        int ci = (i / 90) % 10;
        int to = (i / 900) % 9;
        int br = i / 8100;
        g_W2[i] = (br == 0) ? w2[(co * 10 + ci) * 81 + to * 9 + ti]
                            : w2[(co * 10 + ci) * 81 + ti * 9 + to];
    }
    // W3 interleaved by branch: [to][ci][ti][br2]
    for (int i = tid; i < 1620; i += stride) {
        int br = i % 2;
        int ti = (i / 2) % 9;
        int ci = (i / 18) % 10;
        int to = i / 180;
        g_W3[i] = (br == 0) ? w3[ci * 81 + to * 9 + ti]
                            : w3[ci * 81 + ti * 9 + to];
    }
}

// ---------------------------------------------------------------------------
// conv1: x (1 ch) -> t1 (20 ch), relu.  One CTA per (b,h1,w1), 300 threads.
// Thread tile: all 20 co as 10 f32x2 pairs x 3 w2 positions.
// ---------------------------------------------------------------------------
__global__ __launch_bounds__(300)
void conv1_kernel(const float* __restrict__ x, const float* __restrict__ b1) {
    __shared__ __align__(16) float sIn[32 * 33];
    __shared__ __align__(16) float sW[9 * 9 * 20];
    __shared__ float sB[20];
    int bid = blockIdx.x;
    int b = bid / SP;
    int rem = bid % SP;
    int h1 = rem / SS, w1 = rem % SS;
    int tid = threadIdx.x;

    for (int i = tid; i < 1620; i += 300) sW[i] = g_W1[i];
    if (tid < 20) sB[tid] = b1[tid % 10];
    for (int i = tid; i < 32 * 33; i += 300) sIn[i] = 0.f;

    int h2 = tid / 10;
    int w2_0 = (tid % 10) * 3;

    ull acc[10][3];
#pragma unroll
    for (int c = 0; c < 10; c++)
#pragma unroll
        for (int p = 0; p < 3; p++) acc[c][p] = 0ull;

    const float* xb = x + (size_t)b * S4;

#pragma unroll 1
    for (int to = 0; to < 9; to++) {
        int H = h1 + to / 3 - 1, W = w1 + to % 3 - 1;
        bool ok = ((unsigned)H < SS) && ((unsigned)W < SS);
        const float* plane = xb + (H * SS + W) * SP;
        __syncthreads();
#pragma unroll
        for (int k = 0; k < 3; k++) {
            int i = tid + k * 300;
            int r = i / SS, c2 = i % SS;
            sIn[(r + 1) * 33 + c2 + 1] = ok ? plane[i] : 0.f;
        }
        __syncthreads();
#pragma unroll
        for (int dh2 = 0; dh2 < 3; dh2++) {
            const float* row = &sIn[(h2 + dh2) * 33 + w2_0];
            ull dup[5];
#pragma unroll
            for (int j = 0; j < 5; j++) { float v = row[j]; PACK2(dup[j], v, v); }
#pragma unroll
            for (int dw2 = 0; dw2 < 3; dw2++) {
                const ull* wp = (const ull*)(sW + (to * 9 + dh2 * 3 + dw2) * 20);
#pragma unroll
                for (int c = 0; c < 10; c++) {
                    ull w = wp[c];
#pragma unroll
                    for (int p = 0; p < 3; p++) FMA2(acc[c][p], dup[p + dw2], w);
                }
            }
        }
    }

#pragma unroll
    for (int c = 0; c < 10; c++) {
        int co = 2 * c;
        float b0 = sB[co], b1v = sB[co + 1];
        float* d0 = g_t1 + ((size_t)(b * 20 + co) * SP + h1 * SS + w1) * SP +
                    h2 * SS + w2_0;
        float* d1 = d0 + (size_t)SP * SP;
#pragma unroll
        for (int p = 0; p < 3; p++) {
            float lo, hi;
            UNPACK2(lo, hi, acc[c][p]);
            lo += b0; hi += b1v;
            d0[p] = lo > 0.f ? lo : 0.f;
            d1[p] = hi > 0.f ? hi : 0.f;
        }
    }
}

// ---------------------------------------------------------------------------
// conv2: t1 -> t2 (branch-interleaved), block-diagonal 10->10 per branch, relu.
// One CTA per (b, br, h1, w1), 300 threads.
// Thread tile: 10 co as 5 f32x2 pairs x 3 w2 positions.
// ---------------------------------------------------------------------------
__global__ __launch_bounds__(300)
void conv2_kernel(const float* __restrict__ b2) {
    extern __shared__ __align__(16) float smem2[];
    float* sIn = smem2;          // 10 * 1056
    float* sW = smem2 + 10560;   // 8100
    __shared__ float sB[10];

    int bid = blockIdx.x;
    int w1 = bid % SS;
    int t = bid / SS;
    int h1 = t % SS;
    t /= SS;
    int br = t & 1;
    int b = t >> 1;
    int tid = threadIdx.x;

    for (int i = tid; i < 8100; i += 300) sW[i] = g_W2[br * 8100 + i];
    if (tid < 10) sB[tid] = b2[tid];
    for (int i = tid; i < 10560; i += 300) sIn[i] = 0.f;

    int h2 = tid / 10;
    int w2_0 = (tid % 10) * 3;

    ull acc[5][3];
#pragma unroll
    for (int c = 0; c < 5; c++)
#pragma unroll
        for (int p = 0; p < 3; p++) acc[c][p] = 0ull;

    const float* tbase = g_t1 + (size_t)(b * 20 + br * 10) * S4;

#pragma unroll 1
    for (int to = 0; to < 9; to++) {
        int H = h1 + to / 3 - 1, W = w1 + to % 3 - 1;
        bool ok = ((unsigned)H < SS) && ((unsigned)W < SS);
        int poff = (H * SS + W) * SP;
        __syncthreads();
        // flat staging loop: 30 independent LDGs per thread for MLP
        for (int i = tid; i < 9000; i += 300) {
            int ci = i / 900;
            int j = i - ci * 900;
            int r = j / SS, c2 = j % SS;
            sIn[ci * 1056 + (r + 1) * 33 + c2 + 1] =
                ok ? tbase[(size_t)ci * S4 + poff + j] : 0.f;
        }
        __syncthreads();
#pragma unroll 1
        for (int ci = 0; ci < 10; ci++) {
            const float* sc = sIn + ci * 1056;
            const float* wci = sW + (to * 10 + ci) * 90;  // [ti(9)][co10]
#pragma unroll
            for (int dh2 = 0; dh2 < 3; dh2++) {
                const float* row = sc + (h2 + dh2) * 33 + w2_0;
                ull dup[5];
#pragma unroll
                for (int j = 0; j < 5; j++) { float v = row[j]; PACK2(dup[j], v, v); }
#pragma unroll
                for (int dw2 = 0; dw2 < 3; dw2++) {
                    const ull* wp = (const ull*)(wci + (dh2 * 3 + dw2) * 10);
#pragma unroll
                    for (int c = 0; c < 5; c++) {
                        ull w = wp[c];
#pragma unroll
                        for (int p = 0; p < 3; p++) FMA2(acc[c][p], dup[p + dw2], w);
                    }
                }
            }
        }
    }

    int pos0 = h2 * SS + w2_0;
#pragma unroll
    for (int c = 0; c < 5; c++) {
        int co = 2 * c;
        float b0 = sB[co], b1v = sB[co + 1];
        float* d0 = g_t2 + ((size_t)(b * 10 + co) * SP + h1 * SS + w1) * 1800 +
                    pos0 * 2 + br;
        float* d1 = d0 + (size_t)SP * 1800;
#pragma unroll
        for (int p = 0; p < 3; p++) {
            float lo, hi;
            UNPACK2(lo, hi, acc[c][p]);
            lo += b0; hi += b1v;
            d0[2 * p] = lo > 0.f ? lo : 0.f;
            d1[2 * p] = hi > 0.f ? hi : 0.f;
        }
    }
}

// ---------------------------------------------------------------------------
// conv3 + final sum: t2 (10 ci, branch-interleaved float2) -> out.
// out = relu(convA + b3) + relu(convB + b3).  One CTA per (b,h1,w1).
// Branch pair is carried natively in one f32x2 lane pair; no pack instrs.
// ---------------------------------------------------------------------------
__global__ __launch_bounds__(300)
void conv3_kernel(const float* __restrict__ b3, float* __restrict__ out) {
    extern __shared__ __align__(16) char smraw[];
    double* sD = (double*)smraw;                 // 10 * 1056 float2 planes
    ull* sW3 = (ull*)(smraw + 10 * 1056 * 8);    // 810 (wA,wB) pairs

    int bid = blockIdx.x;
    int b = bid / SP;
    int rem = bid % SP;
    int h1 = rem / SS, w1 = rem % SS;
    int tid = threadIdx.x;

    for (int i = tid; i < 810; i += 300) sW3[i] = ((const ull*)g_W3)[i];
    for (int i = tid; i < 10560; i += 300) sD[i] = 0.0;

    int h2 = tid / 10;
    int w2_0 = (tid % 10) * 3;

    ull acc[3] = {0ull, 0ull, 0ull};
    const double* tb2 = (const double*)g_t2 + (size_t)b * 10 * SP * SP;

#pragma unroll 1
    for (int to = 0; to < 9; to++) {
        int H = h1 + to / 3 - 1, W = w1 + to % 3 - 1;
        bool ok = ((unsigned)H < SS) && ((unsigned)W < SS);
        int poff = H * SS + W;
        __syncthreads();
        for (int i = tid; i < 9000; i += 300) {
            int ci = i / 900;
            int j = i - ci * 900;
            int r = j / SS, c2 = j % SS;
            sD[ci * 1056 + (r + 1) * 33 + c2 + 1] =
                ok ? tb2[((size_t)(ci)*SP + poff) * 900 + j] : 0.0;
        }
        __syncthreads();
#pragma unroll 1
        for (int ci = 0; ci < 10; ci++) {
            const double* sc = sD + ci * 1056;
            const ull* wci = sW3 + (to * 10 + ci) * 9;
#pragma unroll
            for (int dh2 = 0; dh2 < 3; dh2++) {
                const ull* row = (const ull*)(sc + (h2 + dh2) * 33 + w2_0);
                ull a[5];
#pragma unroll
                for (int j = 0; j < 5; j++) a[j] = row[j];
#pragma unroll
                for (int dw2 = 0; dw2 < 3; dw2++) {
                    ull w = wci[dh2 * 3 + dw2];
#pragma unroll
                    for (int p = 0; p < 3; p++) FMA2(acc[p], a[p + dw2], w);
                }
            }
        }
    }

    float bv = b3[0];
    float* dst = out + (size_t)b * S4 + (h1 * SS + w1) * SP + h2 * SS + w2_0;
#pragma unroll
    for (int p = 0; p < 3; p++) {
        float lo, hi;
        UNPACK2(lo, hi, acc[p]);
        float va = lo + bv;
        va = va > 0.f ? va : 0.f;
        float vb = hi + bv;
        vb = vb > 0.f ? vb : 0.f;
        dst[p] = va + vb;
    }
}

// ---------------------------------------------------------------------------
extern "C" void kernel_launch(void* const* d_in, const int* in_sizes, int n_in,
                              void* d_out, int out_size) {
    const float* x = (const float*)d_in[0];
    const float* w1 = (const float*)d_in[1];
    const float* b1 = (const float*)d_in[2];
    const float* w2 = (const float*)d_in[3];
    const float* b2 = (const float*)d_in[4];
    const float* w3 = (const float*)d_in[5];
    const float* b3 = (const float*)d_in[6];
    float* out = (float*)d_out;

    const int smem2 = (10560 + 8100) * 4;          // 74640 B
    const int smem3 = 10 * 1056 * 8 + 810 * 8;     // 90960 B
    cudaFuncSetAttribute(conv2_kernel,
                         cudaFuncAttributeMaxDynamicSharedMemorySize, smem2);
    cudaFuncSetAttribute(conv3_kernel,
                         cudaFuncAttributeMaxDynamicSharedMemorySize, smem3);

    prep_kernel<<<32, 256>>>(w1, w2, w3);
    conv1_kernel<<<NB * SP, 300>>>(x, b1);
    conv2_kernel<<<NB * 2 * SP, 300, smem2>>>(b2);
    conv3_kernel<<<NB * SP, 300, smem3>>>(b3, out);
}

// round 3
// speedup vs baseline: 1.5521x; 1.2110x over previous
#include <cuda_runtime.h>
#include <cstdint>

#define SS 30
#define SP 900          // 30*30
#define S4 810000       // 30^4
#define NB 2

typedef unsigned long long ull;

// Scratch activations
__device__ __align__(16) float g_t1[NB * 20 * S4];                // [b][ch20][h1w1][pos]
__device__ __align__(16) float g_t2[NB * 10 * SP * SP * 2];       // [b][co10][h1w1][pos][br2]
// Packed weights
__device__ __align__(16) float g_W1[9 * 9 * 20];                  // [to][ti][co20]
__device__ __align__(16) float g_W2[2 * 9 * 10 * 9 * 10];         // [br][to][ci][ti][co10]
__device__ __align__(16) float g_W3[9 * 10 * 9 * 2];              // [to][ci][ti][br2]

#define PACK2(d, a, b)  asm("mov.b64 %0, {%1, %2};" : "=l"(d) : "f"(a), "f"(b))
#define FMA2(d, a, b)   asm("fma.rn.f32x2 %0, %1, %2, %0;" : "+l"(d) : "l"(a), "l"(b))
#define ADD2(d, a, b)   asm("add.rn.f32x2 %0, %1, %2;" : "=l"(d) : "l"(a), "l"(b))
#define UNPACK2(lo, hi, d) asm("mov.b64 {%0, %1}, %2;" : "=f"(lo), "=f"(hi) : "l"(d))

__device__ __forceinline__ uint32_t s2u(const void* p) {
    uint32_t a;
    asm("{ .reg .u64 t; cvta.to.shared.u64 t, %1; cvt.u32.u64 %0, t; }"
        : "=r"(a) : "l"(p));
    return a;
}
__device__ __forceinline__ void cpa4(uint32_t s, const void* g, int srcsz) {
    asm volatile("cp.async.ca.shared.global [%0], [%1], 4, %2;"
                 :: "r"(s), "l"(g), "r"(srcsz));
}
__device__ __forceinline__ void cpa8(uint32_t s, const void* g, int srcsz) {
    asm volatile("cp.async.ca.shared.global [%0], [%1], 8, %2;"
                 :: "r"(s), "l"(g), "r"(srcsz));
}
__device__ __forceinline__ void cpa_commit_wait() {
    asm volatile("cp.async.commit_group;");
    asm volatile("cp.async.wait_group 0;" ::: "memory");
}

// ---------------------------------------------------------------------------
// Weight prep.  Branch 1 = kernel dims (h1w1)<->(h2w2) swapped.
// ---------------------------------------------------------------------------
__global__ void prep_kernel(const float* __restrict__ w1,
                            const float* __restrict__ w2,
                            const float* __restrict__ w3) {
    int tid = blockIdx.x * blockDim.x + threadIdx.x;
    int stride = gridDim.x * blockDim.x;
    for (int i = tid; i < 9 * 9 * 20; i += stride) {
        int co = i % 20;
        int ti = (i / 20) % 9;
        int to = i / 180;
        g_W1[i] = (co < 10) ? w1[co * 81 + to * 9 + ti]
                            : w1[(co - 10) * 81 + ti * 9 + to];
    }
    for (int i = tid; i < 16200; i += stride) {
        int co = i % 10;
        int ti = (i / 10) % 9;
        int ci = (i / 90) % 10;
        int to = (i / 900) % 9;
        int br = i / 8100;
        g_W2[i] = (br == 0) ? w2[(co * 10 + ci) * 81 + to * 9 + ti]
                            : w2[(co * 10 + ci) * 81 + ti * 9 + to];
    }
    for (int i = tid; i < 1620; i += stride) {
        int br = i % 2;
        int ti = (i / 2) % 9;
        int ci = (i / 18) % 10;
        int to = i / 180;
        g_W3[i] = (br == 0) ? w3[ci * 81 + to * 9 + ti]
                            : w3[ci * 81 + ti * 9 + to];
    }
}

// ---------------------------------------------------------------------------
// conv1: x (1 ch) -> t1 (20 ch), relu.  One CTA per (b,h1,w1), 300 threads.
// Thread tile: 10 co-pairs (f32x2) x 3 w2 positions.
// ---------------------------------------------------------------------------
__global__ __launch_bounds__(300)
void conv1_kernel(const float* __restrict__ x, const float* __restrict__ b1) {
    __shared__ __align__(16) float sIn[32 * 33];
    __shared__ __align__(16) float sW[9 * 9 * 20];
    __shared__ float sB[20];
    int bid = blockIdx.x;
    int b = bid / SP;
    int rem = bid % SP;
    int h1 = rem / SS, w1 = rem % SS;
    int tid = threadIdx.x;

    {
        const float4* src = (const float4*)g_W1;
        float4* dst = (float4*)sW;
        for (int i = tid; i < 405; i += 300) dst[i] = src[i];
    }
    if (tid < 20) sB[tid] = b1[tid % 10];
    for (int i = tid; i < 32 * 33; i += 300) sIn[i] = 0.f;

    int h2 = tid / 10;
    int w2_0 = (tid % 10) * 3;

    // fixed staging offsets: elements tid, tid+300, tid+600
    int gOff[3], sOff[3];
#pragma unroll
    for (int k = 0; k < 3; k++) {
        int j = tid + k * 300;
        int rr = j / SS, cc = j % SS;
        gOff[k] = j;
        sOff[k] = (rr + 1) * 33 + cc + 1;
    }
    uint32_t sInA = s2u(sIn);

    ull acc[10][3];
#pragma unroll
    for (int c = 0; c < 10; c++)
#pragma unroll
        for (int p = 0; p < 3; p++) acc[c][p] = 0ull;

    const float* xb = x + (size_t)b * S4;

#pragma unroll 1
    for (int to = 0; to < 9; to++) {
        int H = h1 + to / 3 - 1, W = w1 + to % 3 - 1;
        bool ok = ((unsigned)H < SS) && ((unsigned)W < SS);
        int srcsz = ok ? 4 : 0;
        int poff = ok ? (H * SS + W) * SP : 0;
        const float* plane = xb + poff;
        __syncthreads();
#pragma unroll
        for (int k = 0; k < 3; k++)
            cpa4(sInA + sOff[k] * 4, plane + gOff[k], srcsz);
        cpa_commit_wait();
        __syncthreads();
#pragma unroll
        for (int dh2 = 0; dh2 < 3; dh2++) {
            const float* row = &sIn[(h2 + dh2) * 33 + w2_0];
            ull dup[5];
#pragma unroll
            for (int j = 0; j < 5; j++) { float v = row[j]; PACK2(dup[j], v, v); }
#pragma unroll
            for (int dw2 = 0; dw2 < 3; dw2++) {
                const ull* wp = (const ull*)(sW + (to * 9 + dh2 * 3 + dw2) * 20);
#pragma unroll
                for (int c = 0; c < 10; c++) {
                    ull w = wp[c];
#pragma unroll
                    for (int p = 0; p < 3; p++) FMA2(acc[c][p], dup[p + dw2], w);
                }
            }
        }
    }

#pragma unroll
    for (int c = 0; c < 10; c++) {
        int co = 2 * c;
        float b0 = sB[co], b1v = sB[co + 1];
        float* d0 = g_t1 + ((size_t)(b * 20 + co) * SP + h1 * SS + w1) * SP +
                    h2 * SS + w2_0;
        float* d1 = d0 + (size_t)SP * SP;
#pragma unroll
        for (int p = 0; p < 3; p++) {
            float lo, hi;
            UNPACK2(lo, hi, acc[c][p]);
            lo += b0; hi += b1v;
            d0[p] = lo > 0.f ? lo : 0.f;
            d1[p] = hi > 0.f ? hi : 0.f;
        }
    }
}

// ---------------------------------------------------------------------------
// conv2: t1 -> t2 (branch-interleaved), block-diagonal 10->10 per branch, relu.
// One CTA per (b, br, h1, w1), 300 threads = 2 ci-halves x (30 h2 x 5 w2grp(6)).
// Thread tile: 5 co-pairs (f32x2) x 6 w2 positions; ci-halves reduced via smem.
// ---------------------------------------------------------------------------
__global__ __launch_bounds__(300, 2)
void conv2_kernel(const float* __restrict__ b2) {
    extern __shared__ __align__(16) float smem2[];
    float* sIn = smem2;          // 10 * 1056
    float* sW = smem2 + 10560;   // 8100
    __shared__ float sB[10];

    int bid = blockIdx.x;
    int w1 = bid % SS;
    int t = bid / SS;
    int h1 = t % SS;
    t /= SS;
    int br = t & 1;
    int b = t >> 1;
    int tid = threadIdx.x;

    {
        const float4* src = (const float4*)(g_W2 + br * 8100);
        float4* dst = (float4*)sW;
        for (int i = tid; i < 2025; i += 300) dst[i] = src[i];
    }
    if (tid < 10) sB[tid] = b2[tid];
    for (int i = tid; i < 10560; i += 300) sIn[i] = 0.f;

    int cihalf = tid / 150;
    int r = tid % 150;
    int h2 = r / 5;
    int w2_0 = (r % 5) * 6;
    int ci0 = cihalf * 5;

    int gOff[3], sOff[3];
#pragma unroll
    for (int k = 0; k < 3; k++) {
        int j = tid + k * 300;
        int rr = j / SS, cc = j % SS;
        gOff[k] = j;
        sOff[k] = (rr + 1) * 33 + cc + 1;
    }
    uint32_t sInA = s2u(sIn);

    ull acc[5][6];
#pragma unroll
    for (int c = 0; c < 5; c++)
#pragma unroll
        for (int p = 0; p < 6; p++) acc[c][p] = 0ull;

    const float* tbase = g_t1 + (size_t)(b * 20 + br * 10) * S4;

#pragma unroll 1
    for (int to = 0; to < 9; to++) {
        int H = h1 + to / 3 - 1, W = w1 + to % 3 - 1;
        bool ok = ((unsigned)H < SS) && ((unsigned)W < SS);
        int srcsz = ok ? 4 : 0;
        int poff = ok ? (H * SS + W) * SP : 0;
        __syncthreads();
#pragma unroll
        for (int ci = 0; ci < 10; ci++) {
            const float* g = tbase + (size_t)ci * S4 + poff;
            uint32_t sb = sInA + ci * (1056 * 4);
#pragma unroll
            for (int k = 0; k < 3; k++)
                cpa4(sb + sOff[k] * 4, g + gOff[k], srcsz);
        }
        cpa_commit_wait();
        __syncthreads();
#pragma unroll 1
        for (int cc2 = 0; cc2 < 5; cc2++) {
            int ci = ci0 + cc2;
            const float* sc = sIn + ci * 1056;
            const float* wci = sW + (to * 10 + ci) * 90;  // [ti(9)][co10]
#pragma unroll
            for (int dh2 = 0; dh2 < 3; dh2++) {
                const float* rowp = sc + (h2 + dh2) * 33 + w2_0;
                ull dup[8];
#pragma unroll
                for (int j = 0; j < 8; j++) { float v = rowp[j]; PACK2(dup[j], v, v); }
#pragma unroll
                for (int dw2 = 0; dw2 < 3; dw2++) {
                    const ull* wp = (const ull*)(wci + (dh2 * 3 + dw2) * 10);
#pragma unroll
                    for (int c = 0; c < 5; c++) {
                        ull w = wp[c];
#pragma unroll
                        for (int p = 0; p < 6; p++) FMA2(acc[c][p], dup[p + dw2], w);
                    }
                }
            }
        }
    }

    // reduce ci-halves via smem (reuse sIn)
    __syncthreads();
    ull* red = (ull*)sIn;
    if (cihalf) {
#pragma unroll
        for (int c = 0; c < 5; c++)
#pragma unroll
            for (int p = 0; p < 6; p++) red[r * 30 + c * 6 + p] = acc[c][p];
    }
    __syncthreads();
    if (!cihalf) {
        int pos0 = h2 * SS + w2_0;
#pragma unroll
        for (int c = 0; c < 5; c++) {
#pragma unroll
            for (int p = 0; p < 6; p++) {
                ull o = red[r * 30 + c * 6 + p];
                ADD2(acc[c][p], acc[c][p], o);
            }
            int co = 2 * c;
            float b0 = sB[co], b1v = sB[co + 1];
            float* d0 = g_t2 + ((size_t)(b * 10 + co) * SP + h1 * SS + w1) * 1800 +
                        pos0 * 2 + br;
            float* d1 = d0 + (size_t)SP * 1800;
#pragma unroll
            for (int p = 0; p < 6; p++) {
                float lo, hi;
                UNPACK2(lo, hi, acc[c][p]);
                lo += b0; hi += b1v;
                d0[2 * p] = lo > 0.f ? lo : 0.f;
                d1[2 * p] = hi > 0.f ? hi : 0.f;
            }
        }
    }
}

// ---------------------------------------------------------------------------
// conv3 + final sum: t2 (10 ci, branch-interleaved float2) -> out.
// One CTA per (b,h1,w1), 300 threads = 2 ci-halves x (30 h2 x 5 w2grp(6)).
// Branch pair carried natively in f32x2 lanes.
// ---------------------------------------------------------------------------
__global__ __launch_bounds__(300, 2)
void conv3_kernel(const float* __restrict__ b3, float* __restrict__ out) {
    extern __shared__ __align__(16) char smraw[];
    double* sD = (double*)smraw;                 // 10 * 1056 float2 planes
    ull* sW3 = (ull*)(smraw + 10 * 1056 * 8);    // 810 (wA,wB) pairs

    int bid = blockIdx.x;
    int b = bid / SP;
    int rem = bid % SP;
    int h1 = rem / SS, w1 = rem % SS;
    int tid = threadIdx.x;

    for (int i = tid; i < 810; i += 300) sW3[i] = ((const ull*)g_W3)[i];
    for (int i = tid; i < 10560; i += 300) sD[i] = 0.0;

    int cihalf = tid / 150;
    int r = tid % 150;
    int h2 = r / 5;
    int w2_0 = (r % 5) * 6;
    int ci0 = cihalf * 5;

    int gOff[3], sOff[3];
#pragma unroll
    for (int k = 0; k < 3; k++) {
        int j = tid + k * 300;
        int rr = j / SS, cc = j % SS;
        gOff[k] = j;
        sOff[k] = (rr + 1) * 33 + cc + 1;
    }
    uint32_t sDA = s2u(sD);

    ull acc[6];
#pragma unroll
    for (int p = 0; p < 6; p++) acc[p] = 0ull;

    const double* tb2 = (const double*)g_t2 + (size_t)b * 10 * SP * SP;

#pragma unroll 1
    for (int to = 0; to < 9; to++) {
        int H = h1 + to / 3 - 1, W = w1 + to % 3 - 1;
        bool ok = ((unsigned)H < SS) && ((unsigned)W < SS);
        int srcsz = ok ? 8 : 0;
        int poff = ok ? (H * SS + W) : 0;
        __syncthreads();
#pragma unroll
        for (int ci = 0; ci < 10; ci++) {
            const double* g = tb2 + ((size_t)ci * SP + poff) * 900;
            uint32_t sb = sDA + ci * (1056 * 8);
#pragma unroll
            for (int k = 0; k < 3; k++)
                cpa8(sb + sOff[k] * 8, g + gOff[k], srcsz);
        }
        cpa_commit_wait();
        __syncthreads();
#pragma unroll 1
        for (int cc2 = 0; cc2 < 5; cc2++) {
            int ci = ci0 + cc2;
            const double* sc = sD + ci * 1056;
            const ull* wci = sW3 + (to * 10 + ci) * 9;
#pragma unroll
            for (int dh2 = 0; dh2 < 3; dh2++) {
                const ull* rowp = (const ull*)(sc + (h2 + dh2) * 33 + w2_0);
                ull a[8];
#pragma unroll
                for (int j = 0; j < 8; j++) a[j] = rowp[j];
#pragma unroll
                for (int dw2 = 0; dw2 < 3; dw2++) {
                    ull w = wci[dh2 * 3 + dw2];
#pragma unroll
                    for (int p = 0; p < 6; p++) FMA2(acc[p], a[p + dw2], w);
                }
            }
        }
    }

    // reduce ci-halves via smem (reuse sD)
    __syncthreads();
    ull* red = (ull*)sD;
    if (cihalf) {
#pragma unroll
        for (int p = 0; p < 6; p++) red[r * 6 + p] = acc[p];
    }
    __syncthreads();
    if (!cihalf) {
        float bv = b3[0];
        float* dst = out + (size_t)b * S4 + (h1 * SS + w1) * SP + h2 * SS + w2_0;
#pragma unroll
        for (int p = 0; p < 6; p++) {
            ull o = red[r * 6 + p];
            ADD2(acc[p], acc[p], o);
            float lo, hi;
            UNPACK2(lo, hi, acc[p]);
            float va = lo + bv;
            va = va > 0.f ? va : 0.f;
            float vb = hi + bv;
            vb = vb > 0.f ? vb : 0.f;
            dst[p] = va + vb;
        }
    }
}

// ---------------------------------------------------------------------------
extern "C" void kernel_launch(void* const* d_in, const int* in_sizes, int n_in,
                              void* d_out, int out_size) {
    const float* x = (const float*)d_in[0];
    const float* w1 = (const float*)d_in[1];
    const float* b1 = (const float*)d_in[2];
    const float* w2 = (const float*)d_in[3];
    const float* b2 = (const float*)d_in[4];
    const float* w3 = (const float*)d_in[5];
    const float* b3 = (const float*)d_in[6];
    float* out = (float*)d_out;

    const int smem2 = (10560 + 8100) * 4;          // 74640 B
    const int smem3 = 10 * 1056 * 8 + 810 * 8;     // 90960 B
    cudaFuncSetAttribute(conv2_kernel,
                         cudaFuncAttributeMaxDynamicSharedMemorySize, smem2);
    cudaFuncSetAttribute(conv3_kernel,
                         cudaFuncAttributeMaxDynamicSharedMemorySize, smem3);

    prep_kernel<<<32, 256>>>(w1, w2, w3);
    conv1_kernel<<<NB * SP, 300>>>(x, b1);
    conv2_kernel<<<NB * 2 * SP, 300, smem2>>>(b2);
    conv3_kernel<<<NB * SP, 300, smem3>>>(b3, out);
}